// round 12
// baseline (speedup 1.0000x reference)
#include <cuda_runtime.h>
#include <stdint.h>
#include <math.h>
#include <mma.h>

using namespace nvcuda;

#define BB 2
#define TT 2048
#define DD 1024
#define HH 16
#define DH 64
#define BT (BB*TT)

// Scratch (allocation-free rule: __device__ globals)
__device__ float g_qkv[(size_t)BT * 3 * DD];
__device__ float g_q[(size_t)BT * DD];   // [B,H,T,DH]
__device__ float g_k[(size_t)BT * DD];
__device__ float g_v[(size_t)BT * DD];
__device__ float g_att[(size_t)BT * DD]; // [B*T, D], tf32-rounded by flash
__device__ float g_xr[(size_t)BT * DD];        // x rounded to tf32
__device__ float g_w1r[(size_t)DD * 3 * DD];   // Wqkv rounded
__device__ float g_w2r[(size_t)DD * DD];       // Wout rounded

// ---------------------------------------------------------------------------
// helpers
// ---------------------------------------------------------------------------
__device__ __forceinline__ void cp_async16(void* dst, const void* src) {
    unsigned int d = (unsigned int)__cvta_generic_to_shared(dst);
    asm volatile("cp.async.ca.shared.global [%0], [%1], 16;\n" :: "r"(d), "l"(src));
}
__device__ __forceinline__ void cp_commit() {
    asm volatile("cp.async.commit_group;\n");
}
__device__ __forceinline__ void cp_wait1() {
    asm volatile("cp.async.wait_group 1;\n");
}
__device__ __forceinline__ float to_tf32(float x) {
    float r;
    asm("cvt.rna.tf32.f32 %0, %1;" : "=f"(r) : "f"(x));
    return r;
}
// Fast exp for x <= 0: FFMA/ALU only. rel err ~2e-6.
__device__ __forceinline__ float fexp(float x) {
    float t = fmaxf(x * 1.4426950408889634f, -126.0f);
    float tr = t + 12582912.0f;
    int   n  = __float_as_int(tr) - 0x4B400000;
    float f  = t - (tr - 12582912.0f);
    float p = 0.0013333558f;
    p = fmaf(p, f, 0.0096181291f);
    p = fmaf(p, f, 0.0555041087f);
    p = fmaf(p, f, 0.2402265069f);
    p = fmaf(p, f, 0.6931471806f);
    p = fmaf(p, f, 1.0f);
    return p * __int_as_float((n + 127) << 23);
}

// Elementwise tf32 rounding (memory-bound, run once per buffer)
__global__ __launch_bounds__(256)
void round_tf32_kernel(const float* __restrict__ in, float* __restrict__ out, int n4) {
    int i = blockIdx.x * blockDim.x + threadIdx.x;
    if (i >= n4) return;
    float4 v = ((const float4*)in)[i];
    v.x = to_tf32(v.x); v.y = to_tf32(v.y);
    v.z = to_tf32(v.z); v.w = to_tf32(v.w);
    ((float4*)out)[i] = v;
}

// ---------------------------------------------------------------------------
// TF32 tensor-core GEMM v2: CTA 128x128, FOUR warps, warp tile 64x64
// (4x4 wmma frags). Per 8-kk step: 8 frag loads -> 16 mmas (2x better
// mma:load ratio). BK=16, 3-stage cp.async, 2 CTAs/SM.
// Inputs pre-rounded to tf32 (no in-loop cvt).
// ---------------------------------------------------------------------------
#define BMg 128
#define BNg 128
#define BKg 16
#define STAGES 3
#define A_STRIDE (BKg + 4)
#define B_STRIDE (BNg + 4)
#define AS_TILE (BMg * A_STRIDE)
#define BS_TILE (BKg * B_STRIDE)
#define SMEM_GEMM ((STAGES * (AS_TILE + BS_TILE)) * 4)

__global__ __launch_bounds__(128, 2)
void gemm_tf32_bias(const float* __restrict__ A, const float* __restrict__ B,
                    const float* __restrict__ bias, float* __restrict__ C,
                    int M, int N, int K) {
    extern __shared__ float smg[];
    float* AsBase = smg;
    float* BsBase = smg + STAGES * AS_TILE;

    int tid  = threadIdx.x;
    int wid  = tid >> 5;
    int lane = tid & 31;
    int warp_m = wid & 1;        // 0..1 -> 64 rows each
    int warp_n = wid >> 1;       // 0..1 -> 64 cols each
    int brow = blockIdx.y * BMg;
    int bcol = blockIdx.x * BNg;

    // Load mappings (128 threads)
    int a_row = tid;               // 0..127, 16 floats each
    int b_row = tid >> 3;          // 0..15
    int b_col = (tid & 7) * 16;    // 0..112, 16 floats each

    const float* Ap = A + (size_t)(brow + a_row) * K;
    const float* Bp = B + (size_t)b_row * N + bcol + b_col;

    wmma::fragment<wmma::accumulator, 16, 16, 8, float> acc[4][4];
#pragma unroll
    for (int i = 0; i < 4; i++)
#pragma unroll
        for (int j = 0; j < 4; j++) wmma::fill_fragment(acc[i][j], 0.0f);

    const int iters = K / BKg;

#pragma unroll
    for (int s = 0; s < STAGES - 1; s++) {
        int k0 = s * BKg;
        float* As = AsBase + s * AS_TILE;
        float* Bs = BsBase + s * BS_TILE;
#pragma unroll
        for (int u = 0; u < 4; u++) {
            cp_async16(&As[a_row * A_STRIDE + u * 4],         Ap + k0 + u * 4);
            cp_async16(&Bs[b_row * B_STRIDE + b_col + u * 4], Bp + (size_t)k0 * N + u * 4);
        }
        cp_commit();
    }

    for (int it = 0; it < iters; it++) {
        cp_wait1();
        __syncthreads();

        int buf = it % STAGES;
        float* As = AsBase + buf * AS_TILE;
        float* Bs = BsBase + buf * BS_TILE;

#pragma unroll
        for (int kk = 0; kk < BKg; kk += 8) {
            wmma::fragment<wmma::matrix_a, 16, 16, 8, wmma::precision::tf32, wmma::row_major> af[4];
            wmma::fragment<wmma::matrix_b, 16, 16, 8, wmma::precision::tf32, wmma::row_major> bf[4];
#pragma unroll
            for (int i = 0; i < 4; i++)
                wmma::load_matrix_sync(af[i], &As[(warp_m * 64 + i * 16) * A_STRIDE + kk], A_STRIDE);
#pragma unroll
            for (int j = 0; j < 4; j++)
                wmma::load_matrix_sync(bf[j], &Bs[kk * B_STRIDE + warp_n * 64 + j * 16], B_STRIDE);
#pragma unroll
            for (int i = 0; i < 4; i++)
#pragma unroll
                for (int j = 0; j < 4; j++)
                    wmma::mma_sync(acc[i][j], af[i], bf[j], acc[i][j]);
        }

        int k_next = (it + STAGES - 1) * BKg;
        if (k_next < K) {
            int s = (it + STAGES - 1) % STAGES;
            float* Asn = AsBase + s * AS_TILE;
            float* Bsn = BsBase + s * BS_TILE;
#pragma unroll
            for (int u = 0; u < 4; u++) {
                cp_async16(&Asn[a_row * A_STRIDE + u * 4],         Ap + k_next + u * 4);
                cp_async16(&Bsn[b_row * B_STRIDE + b_col + u * 4], Bp + (size_t)k_next * N + u * 4);
            }
        }
        cp_commit();
    }

    // Epilogue: stage each 16x16 fragment through smem, add bias, write global
    __syncthreads();
    float* stg = AsBase + wid * 16 * 24;

    int er = lane >> 1;
    int ec = (lane & 1) * 8;
#pragma unroll
    for (int i = 0; i < 4; i++) {
#pragma unroll
        for (int j = 0; j < 4; j++) {
            wmma::store_matrix_sync(stg, acc[i][j], 24, wmma::mem_row_major);
            __syncwarp();
            int gr = brow + warp_m * 64 + i * 16 + er;
            int gc = bcol + warp_n * 64 + j * 16 + ec;
            float4 v0 = *(float4*)&stg[er * 24 + ec];
            float4 v1 = *(float4*)&stg[er * 24 + ec + 4];
            const float4 bb0 = *(const float4*)&bias[gc];
            const float4 bb1 = *(const float4*)&bias[gc + 4];
            v0.x += bb0.x; v0.y += bb0.y; v0.z += bb0.z; v0.w += bb0.w;
            v1.x += bb1.x; v1.y += bb1.y; v1.z += bb1.z; v1.w += bb1.w;
            *(float4*)(C + (size_t)gr * N + gc)     = v0;
            *(float4*)(C + (size_t)gr * N + gc + 4) = v1;
            __syncwarp();
        }
    }
}

// ---------------------------------------------------------------------------
// RoPE + split qkv[BT, 3D] -> Q,K,V in [B,H,T,DH]
// ---------------------------------------------------------------------------
__global__ __launch_bounds__(256)
void rope_split_kernel(const float* __restrict__ qkv,
                       float* __restrict__ Q, float* __restrict__ K,
                       float* __restrict__ V) {
    int idx = blockIdx.x * blockDim.x + threadIdx.x;
    const int total = BB * TT * HH * (DH / 2);
    if (idx >= total) return;
    int d2 = idx & 31;
    int h  = (idx >> 5) & (HH - 1);
    int t  = (idx >> 9) & (TT - 1);
    int b  = idx >> 20;

    size_t row = (size_t)b * TT + t;
    const float* qr = qkv + row * (3 * DD) + h * DH + 2 * d2;
    const float* kr = qr + DD;
    const float* vr = qr + 2 * DD;

    float inv_freq = powf(10000.0f, -((float)(2 * d2)) / (float)DH);
    float freq = (float)t * inv_freq;
    float s = sinf(freq);
    float c = cosf(freq);

    float qe = qr[0], qo = qr[1];
    float ke = kr[0], ko = kr[1];

    size_t o = ((((size_t)b * HH + h) * TT) + t) * DH + 2 * d2;
    Q[o]     = qe * c - qo * s;
    Q[o + 1] = qe * s + qo * c;
    K[o]     = ke * c - ko * s;
    K[o + 1] = ke * s + ko * c;
    V[o]     = vr[0];
    V[o + 1] = vr[1];
}

// ---------------------------------------------------------------------------
// Tiled flash attention (R6 kernel, measured best): 64-query tile,
// 256 threads, scalar 4x4 register tile GEMMs, fexp softmax.
// Epilogue rounds output to tf32 (out-proj input is pre-rounded).
// ---------------------------------------------------------------------------
#define QS_STRIDE 65
#define VS_STRIDE 68
#define SMEM_FLASH ((2 * 64 * QS_STRIDE + 64 * VS_STRIDE) * 4 + 64 * 4)

__device__ __forceinline__ void load_tile_T(const float* __restrict__ src,
                                            float* __restrict__ dst,
                                            int tid, float mul) {
    int r = tid >> 2;
    int cbase = (tid & 3) * 4;
#pragma unroll
    for (int rep = 0; rep < 4; rep++) {
        int c = cbase + rep * 16;
        float4 v = *(const float4*)(src + r * 64 + c);
        dst[(c + 0) * QS_STRIDE + r] = v.x * mul;
        dst[(c + 1) * QS_STRIDE + r] = v.y * mul;
        dst[(c + 2) * QS_STRIDE + r] = v.z * mul;
        dst[(c + 3) * QS_STRIDE + r] = v.w * mul;
    }
}

__global__ __launch_bounds__(256)
void flash_attn_tiled(const float* __restrict__ Q, const float* __restrict__ K,
                      const float* __restrict__ V, const int* __restrict__ mask,
                      float* __restrict__ Out) {
    extern __shared__ float sm[];
    float* Qs  = sm;
    float* KPs = sm + 64 * QS_STRIDE;
    float* Vs  = sm + 2 * 64 * QS_STRIDE;
    int*   ms  = (int*)(sm + 2 * 64 * QS_STRIDE + 64 * VS_STRIDE);

    int b = blockIdx.z, h = blockIdx.y;
    int qtile = gridDim.x - 1 - blockIdx.x;
    int qbase = qtile * 64;
    int tid = threadIdx.x;
    int ty = tid >> 4;
    int tx = tid & 15;

    const size_t bh = ((size_t)b * HH + h) * TT;
    const float* Qb = Q + bh * DH;
    const float* Kb = K + bh * DH;
    const float* Vb = V + bh * DH;

    load_tile_T(Qb + (size_t)qbase * DH, Qs, tid, 0.125f);

    float acc_o[4][4];
    float m_r[4], l_r[4];
#pragma unroll
    for (int i = 0; i < 4; i++) {
        m_r[i] = -1e30f;
        l_r[i] = 0.f;
#pragma unroll
        for (int j = 0; j < 4; j++) acc_o[i][j] = 0.f;
    }

    for (int kt = 0; kt <= qbase; kt += 64) {
        __syncthreads();

        load_tile_T(Kb + (size_t)kt * DH, KPs, tid, 1.0f);
        {
            int j = tid >> 4;
            int c = (tid & 15) * 4;
#pragma unroll
            for (int rep = 0; rep < 4; rep++) {
                float4 v = *(const float4*)(Vb + (size_t)(kt + j + rep * 16) * DH + c);
                *(float4*)&Vs[(j + rep * 16) * VS_STRIDE + c] = v;
            }
        }
        if (tid < 64) ms[tid] = mask[b * TT + kt + tid];
        __syncthreads();

        float acc_s[4][4];
#pragma unroll
        for (int i = 0; i < 4; i++)
#pragma unroll
            for (int j = 0; j < 4; j++) acc_s[i][j] = 0.f;

        for (int kk = 0; kk < 64; kk++) {
            float ra[4], rb[4];
#pragma unroll
            for (int i = 0; i < 4; i++) ra[i] = Qs[kk * QS_STRIDE + ty * 4 + i];
#pragma unroll
            for (int j = 0; j < 4; j++) rb[j] = KPs[kk * QS_STRIDE + tx * 4 + j];
#pragma unroll
            for (int i = 0; i < 4; i++)
#pragma unroll
                for (int j = 0; j < 4; j++) acc_s[i][j] += ra[i] * rb[j];
        }
        __syncthreads();

        bool diag = (kt == qbase);

#pragma unroll
        for (int i = 0; i < 4; i++) {
            int il = ty * 4 + i;
            float rmax = -1e30f;
#pragma unroll
            for (int j = 0; j < 4; j++) {
                int jl = tx * 4 + j;
                bool ok = (ms[jl] != 0) && (!diag || jl <= il);
                float s = ok ? acc_s[i][j] : -1e30f;
                acc_s[i][j] = s;
                rmax = fmaxf(rmax, s);
            }
#pragma unroll
            for (int off = 8; off >= 1; off >>= 1)
                rmax = fmaxf(rmax, __shfl_xor_sync(0xffffffffu, rmax, off, 16));
            float m_new = fmaxf(m_r[i], rmax);
            float rsum = 0.f;
#pragma unroll
            for (int j = 0; j < 4; j++) {
                float p = fexp(acc_s[i][j] - m_new);
                acc_s[i][j] = p;
                rsum += p;
            }
#pragma unroll
            for (int off = 8; off >= 1; off >>= 1)
                rsum += __shfl_xor_sync(0xffffffffu, rsum, off, 16);
            float scale = fexp(m_r[i] - m_new);
            l_r[i] = l_r[i] * scale + rsum;
            m_r[i] = m_new;
#pragma unroll
            for (int j = 0; j < 4; j++) acc_o[i][j] *= scale;
        }

#pragma unroll
        for (int i = 0; i < 4; i++)
#pragma unroll
            for (int j = 0; j < 4; j++)
                KPs[(ty * 4 + i) * QS_STRIDE + tx * 4 + j] = acc_s[i][j];
        __syncthreads();

        for (int j = 0; j < 64; j++) {
            float4 vb = *(const float4*)&Vs[j * VS_STRIDE + tx * 4];
            float pa[4];
#pragma unroll
            for (int i = 0; i < 4; i++) pa[i] = KPs[(ty * 4 + i) * QS_STRIDE + j];
#pragma unroll
            for (int i = 0; i < 4; i++) {
                acc_o[i][0] += pa[i] * vb.x;
                acc_o[i][1] += pa[i] * vb.y;
                acc_o[i][2] += pa[i] * vb.z;
                acc_o[i][3] += pa[i] * vb.w;
            }
        }
    }

    // Epilogue: normalize, round to tf32 (feeds pre-rounded out-projection)
#pragma unroll
    for (int i = 0; i < 4; i++) {
        int il = ty * 4 + i;
        float inv = (l_r[i] > 0.f) ? (1.0f / l_r[i]) : 0.f;
        float4 o4;
        o4.x = to_tf32(acc_o[i][0] * inv);
        o4.y = to_tf32(acc_o[i][1] * inv);
        o4.z = to_tf32(acc_o[i][2] * inv);
        o4.w = to_tf32(acc_o[i][3] * inv);
        *(float4*)(Out + ((size_t)(b * TT + qbase + il)) * DD + h * DH + tx * 4) = o4;
    }
}

// ---------------------------------------------------------------------------
extern "C" void kernel_launch(void* const* d_in, const int* in_sizes, int n_in,
                              void* d_out, int out_size) {
    const float* x     = (const float*)d_in[0];
    const int*   amask = (const int*)d_in[1];
    const float* Wqkv  = (const float*)d_in[2];
    const float* bqkv  = (const float*)d_in[3];
    const float* Wout  = (const float*)d_in[4];
    const float* bout  = (const float*)d_in[5];
    float* out = (float*)d_out;

    float *qkv, *Qp, *Kp, *Vp, *Att, *xr, *w1r, *w2r;
    cudaGetSymbolAddress((void**)&qkv, g_qkv);
    cudaGetSymbolAddress((void**)&Qp,  g_q);
    cudaGetSymbolAddress((void**)&Kp,  g_k);
    cudaGetSymbolAddress((void**)&Vp,  g_v);
    cudaGetSymbolAddress((void**)&Att, g_att);
    cudaGetSymbolAddress((void**)&xr,  g_xr);
    cudaGetSymbolAddress((void**)&w1r, g_w1r);
    cudaGetSymbolAddress((void**)&w2r, g_w2r);

    static bool attr_set = false;
    if (!attr_set) {
        cudaFuncSetAttribute(flash_attn_tiled,
                             cudaFuncAttributeMaxDynamicSharedMemorySize,
                             SMEM_FLASH);
        cudaFuncSetAttribute(gemm_tf32_bias,
                             cudaFuncAttributeMaxDynamicSharedMemorySize,
                             SMEM_GEMM);
        attr_set = true;
    }

    // 0) Round GEMM inputs to tf32 once (memory-bound, ~25 us)
    {
        int n4;
        n4 = (BT * DD) / 4;
        round_tf32_kernel<<<(n4 + 255) / 256, 256>>>(x, xr, n4);
        n4 = (DD * 3 * DD) / 4;
        round_tf32_kernel<<<(n4 + 255) / 256, 256>>>(Wqkv, w1r, n4);
        n4 = (DD * DD) / 4;
        round_tf32_kernel<<<(n4 + 255) / 256, 256>>>(Wout, w2r, n4);
    }
    // 1) QKV projection (64x64 warp-tile wmma)
    {
        dim3 grid(3 * DD / BNg, BT / BMg);
        gemm_tf32_bias<<<grid, 128, SMEM_GEMM>>>(xr, w1r, bqkv, qkv, BT, 3 * DD, DD);
    }
    // 2) RoPE + split
    {
        int total = BB * TT * HH * (DH / 2);
        rope_split_kernel<<<(total + 255) / 256, 256>>>(qkv, Qp, Kp, Vp);
    }
    // 3) Tiled flash attention (R6 kernel)
    {
        dim3 grid(TT / 64, HH, BB);
        flash_attn_tiled<<<grid, 256, SMEM_FLASH>>>(Qp, Kp, Vp, amask, Att);
    }
    // 4) Output projection
    {
        dim3 grid(DD / BNg, BT / BMg);
        gemm_tf32_bias<<<grid, 128, SMEM_GEMM>>>(Att, w2r, bout, out, BT, DD, DD);
    }
}

// round 14
// speedup vs baseline: 1.4679x; 1.4679x over previous
#include <cuda_runtime.h>
#include <stdint.h>
#include <math.h>
#include <mma.h>
#include <cuda_fp16.h>

using namespace nvcuda;

#define BB 2
#define TT 2048
#define DD 1024
#define HH 16
#define DH 64
#define BT (BB*TT)

// Scratch (allocation-free rule: __device__ globals)
__device__ float g_qkv[(size_t)BT * 3 * DD];
__device__ float g_q[(size_t)BT * DD];   // [B,H,T,DH]
__device__ float g_k[(size_t)BT * DD];
__device__ float g_v[(size_t)BT * DD];
__device__ __half g_xh[(size_t)BT * DD];        // x as fp16
__device__ __half g_w1h[(size_t)DD * 3 * DD];   // Wqkv as fp16 [K][N]
__device__ __half g_w2h[(size_t)DD * DD];       // Wout as fp16 [K][N]
__device__ __half g_atth[(size_t)BT * DD];      // att as fp16 (from flash)

// ---------------------------------------------------------------------------
// helpers
// ---------------------------------------------------------------------------
__device__ __forceinline__ void cp_async16(void* dst, const void* src) {
    unsigned int d = (unsigned int)__cvta_generic_to_shared(dst);
    asm volatile("cp.async.ca.shared.global [%0], [%1], 16;\n" :: "r"(d), "l"(src));
}
__device__ __forceinline__ void cp_commit() {
    asm volatile("cp.async.commit_group;\n");
}
__device__ __forceinline__ void cp_wait1() {
    asm volatile("cp.async.wait_group 1;\n");
}
// Fast exp for x <= 0: FFMA/ALU only. rel err ~2e-6.
__device__ __forceinline__ float fexp(float x) {
    float t = fmaxf(x * 1.4426950408889634f, -126.0f);
    float tr = t + 12582912.0f;
    int   n  = __float_as_int(tr) - 0x4B400000;
    float f  = t - (tr - 12582912.0f);
    float p = 0.0013333558f;
    p = fmaf(p, f, 0.0096181291f);
    p = fmaf(p, f, 0.0555041087f);
    p = fmaf(p, f, 0.2402265069f);
    p = fmaf(p, f, 0.6931471806f);
    p = fmaf(p, f, 1.0f);
    return p * __int_as_float((n + 127) << 23);
}

// Elementwise f32 -> fp16 conversion (memory-bound, run once per buffer)
__global__ __launch_bounds__(256)
void to_half_kernel(const float* __restrict__ in, __half* __restrict__ out, int n4) {
    int i = blockIdx.x * blockDim.x + threadIdx.x;
    if (i >= n4) return;
    float4 v = ((const float4*)in)[i];
    __half2 h0 = __floats2half2_rn(v.x, v.y);
    __half2 h1 = __floats2half2_rn(v.z, v.w);
    uint2 pk;
    pk.x = *(unsigned*)&h0;
    pk.y = *(unsigned*)&h1;
    ((uint2*)out)[i] = pk;
}

// ---------------------------------------------------------------------------
// FP16 tensor-core GEMM: C[M,N] = A[M,K] @ B[K,N] + bias[N]
// wmma m16n16k16 half, fp32 accum. 128x128 CTA tile, 8 warps (4x2),
// warp tile 32x64 = 2x4 frags. BK=32, 3-stage cp.async, 2 CTAs/SM.
// ---------------------------------------------------------------------------
#define BMg 128
#define BNg 128
#define BKh 32
#define STAGES 3
#define A_ST 40    // halfs (80B, 16B multiple)
#define B_ST 136   // halfs (272B, 16B multiple)
#define AS_T (BMg * A_ST)
#define BS_T (BKh * B_ST)
#define SMEM_GH ((STAGES * (AS_T + BS_T)) * 2)

__global__ __launch_bounds__(256, 2)
void gemm_fp16_bias(const __half* __restrict__ A, const __half* __restrict__ B,
                    const float* __restrict__ bias, float* __restrict__ C,
                    int M, int N, int K) {
    extern __shared__ __half smh[];
    __half* AsBase = smh;
    __half* BsBase = smh + STAGES * AS_T;

    int tid  = threadIdx.x;
    int wid  = tid >> 5;
    int lane = tid & 31;
    int warp_m = wid & 3;        // 0..3 -> 32 rows each
    int warp_n = wid >> 2;       // 0..1 -> 64 cols each
    int brow = blockIdx.y * BMg;
    int bcol = blockIdx.x * BNg;

    // A tile: 128 rows x 64B; each thread 2x16B
    int a_row = tid >> 1;
    int a_col = (tid & 1) * 16;        // halfs
    // B tile: 32 rows x 256B; each thread 2x16B
    int b_row = tid >> 3;              // 0..31
    int b_col = (tid & 7) * 16;        // halfs

    const __half* Ap = A + (size_t)(brow + a_row) * K + a_col;
    const __half* Bp = B + (size_t)b_row * N + bcol + b_col;

    wmma::fragment<wmma::accumulator, 16, 16, 16, float> acc[2][4];
#pragma unroll
    for (int i = 0; i < 2; i++)
#pragma unroll
        for (int j = 0; j < 4; j++) wmma::fill_fragment(acc[i][j], 0.0f);

    const int iters = K / BKh;

#pragma unroll
    for (int s = 0; s < STAGES - 1; s++) {
        int k0 = s * BKh;
        __half* As = AsBase + s * AS_T;
        __half* Bs = BsBase + s * BS_T;
        cp_async16(&As[a_row * A_ST + a_col],     Ap + k0);
        cp_async16(&As[a_row * A_ST + a_col + 8], Ap + k0 + 8);
        cp_async16(&Bs[b_row * B_ST + b_col],     Bp + (size_t)k0 * N);
        cp_async16(&Bs[b_row * B_ST + b_col + 8], Bp + (size_t)k0 * N + 8);
        cp_commit();
    }

    for (int it = 0; it < iters; it++) {
        cp_wait1();
        __syncthreads();

        int buf = it % STAGES;
        __half* As = AsBase + buf * AS_T;
        __half* Bs = BsBase + buf * BS_T;

#pragma unroll
        for (int kk = 0; kk < BKh; kk += 16) {
            wmma::fragment<wmma::matrix_a, 16, 16, 16, __half, wmma::row_major> af[2];
            wmma::fragment<wmma::matrix_b, 16, 16, 16, __half, wmma::row_major> bf[4];
#pragma unroll
            for (int i = 0; i < 2; i++)
                wmma::load_matrix_sync(af[i], &As[(warp_m * 32 + i * 16) * A_ST + kk], A_ST);
#pragma unroll
            for (int j = 0; j < 4; j++)
                wmma::load_matrix_sync(bf[j], &Bs[kk * B_ST + warp_n * 64 + j * 16], B_ST);
#pragma unroll
            for (int i = 0; i < 2; i++)
#pragma unroll
                for (int j = 0; j < 4; j++)
                    wmma::mma_sync(acc[i][j], af[i], bf[j], acc[i][j]);
        }

        int k_next = (it + STAGES - 1) * BKh;
        if (k_next < K) {
            int s = (it + STAGES - 1) % STAGES;
            __half* Asn = AsBase + s * AS_T;
            __half* Bsn = BsBase + s * BS_T;
            cp_async16(&Asn[a_row * A_ST + a_col],     Ap + k_next);
            cp_async16(&Asn[a_row * A_ST + a_col + 8], Ap + k_next + 8);
            cp_async16(&Bsn[b_row * B_ST + b_col],     Bp + (size_t)k_next * N);
            cp_async16(&Bsn[b_row * B_ST + b_col + 8], Bp + (size_t)k_next * N + 8);
        }
        cp_commit();
    }

    // Epilogue: stage fragments through smem (reuse As region as f32), add bias
    __syncthreads();
    float* stg = (float*)smh + wid * 16 * 24;

    int er = lane >> 1;
    int ec = (lane & 1) * 8;
#pragma unroll
    for (int i = 0; i < 2; i++) {
#pragma unroll
        for (int j = 0; j < 4; j++) {
            wmma::store_matrix_sync(stg, acc[i][j], 24, wmma::mem_row_major);
            __syncwarp();
            int gr = brow + warp_m * 32 + i * 16 + er;
            int gc = bcol + warp_n * 64 + j * 16 + ec;
            float4 v0 = *(float4*)&stg[er * 24 + ec];
            float4 v1 = *(float4*)&stg[er * 24 + ec + 4];
            const float4 bb0 = *(const float4*)&bias[gc];
            const float4 bb1 = *(const float4*)&bias[gc + 4];
            v0.x += bb0.x; v0.y += bb0.y; v0.z += bb0.z; v0.w += bb0.w;
            v1.x += bb1.x; v1.y += bb1.y; v1.z += bb1.z; v1.w += bb1.w;
            *(float4*)(C + (size_t)gr * N + gc)     = v0;
            *(float4*)(C + (size_t)gr * N + gc + 4) = v1;
            __syncwarp();
        }
    }
}

// ---------------------------------------------------------------------------
// RoPE + split qkv[BT, 3D] -> Q,K,V in [B,H,T,DH]
// ---------------------------------------------------------------------------
__global__ __launch_bounds__(256)
void rope_split_kernel(const float* __restrict__ qkv,
                       float* __restrict__ Q, float* __restrict__ K,
                       float* __restrict__ V) {
    int idx = blockIdx.x * blockDim.x + threadIdx.x;
    const int total = BB * TT * HH * (DH / 2);
    if (idx >= total) return;
    int d2 = idx & 31;
    int h  = (idx >> 5) & (HH - 1);
    int t  = (idx >> 9) & (TT - 1);
    int b  = idx >> 20;

    size_t row = (size_t)b * TT + t;
    const float* qr = qkv + row * (3 * DD) + h * DH + 2 * d2;
    const float* kr = qr + DD;
    const float* vr = qr + 2 * DD;

    float inv_freq = powf(10000.0f, -((float)(2 * d2)) / (float)DH);
    float freq = (float)t * inv_freq;
    float s = sinf(freq);
    float c = cosf(freq);

    float qe = qr[0], qo = qr[1];
    float ke = kr[0], ko = kr[1];

    size_t o = ((((size_t)b * HH + h) * TT) + t) * DH + 2 * d2;
    Q[o]     = qe * c - qo * s;
    Q[o + 1] = qe * s + qo * c;
    K[o]     = ke * c - ko * s;
    K[o + 1] = ke * s + ko * c;
    V[o]     = vr[0];
    V[o + 1] = vr[1];
}

// ---------------------------------------------------------------------------
// Tiled flash attention (R6 kernel, measured best): 64-query tile,
// 256 threads, scalar 4x4 register tile GEMMs, fexp softmax.
// Epilogue writes att as fp16 (feeds the fp16 out-projection).
// ---------------------------------------------------------------------------
#define QS_STRIDE 65
#define VS_STRIDE 68
#define SMEM_FLASH ((2 * 64 * QS_STRIDE + 64 * VS_STRIDE) * 4 + 64 * 4)

__device__ __forceinline__ void load_tile_T(const float* __restrict__ src,
                                            float* __restrict__ dst,
                                            int tid, float mul) {
    int r = tid >> 2;
    int cbase = (tid & 3) * 4;
#pragma unroll
    for (int rep = 0; rep < 4; rep++) {
        int c = cbase + rep * 16;
        float4 v = *(const float4*)(src + r * 64 + c);
        dst[(c + 0) * QS_STRIDE + r] = v.x * mul;
        dst[(c + 1) * QS_STRIDE + r] = v.y * mul;
        dst[(c + 2) * QS_STRIDE + r] = v.z * mul;
        dst[(c + 3) * QS_STRIDE + r] = v.w * mul;
    }
}

__global__ __launch_bounds__(256)
void flash_attn_tiled(const float* __restrict__ Q, const float* __restrict__ K,
                      const float* __restrict__ V, const int* __restrict__ mask,
                      __half* __restrict__ Out) {
    extern __shared__ float sm[];
    float* Qs  = sm;
    float* KPs = sm + 64 * QS_STRIDE;
    float* Vs  = sm + 2 * 64 * QS_STRIDE;
    int*   ms  = (int*)(sm + 2 * 64 * QS_STRIDE + 64 * VS_STRIDE);

    int b = blockIdx.z, h = blockIdx.y;
    int qtile = gridDim.x - 1 - blockIdx.x;
    int qbase = qtile * 64;
    int tid = threadIdx.x;
    int ty = tid >> 4;
    int tx = tid & 15;

    const size_t bh = ((size_t)b * HH + h) * TT;
    const float* Qb = Q + bh * DH;
    const float* Kb = K + bh * DH;
    const float* Vb = V + bh * DH;

    load_tile_T(Qb + (size_t)qbase * DH, Qs, tid, 0.125f);

    float acc_o[4][4];
    float m_r[4], l_r[4];
#pragma unroll
    for (int i = 0; i < 4; i++) {
        m_r[i] = -1e30f;
        l_r[i] = 0.f;
#pragma unroll
        for (int j = 0; j < 4; j++) acc_o[i][j] = 0.f;
    }

    for (int kt = 0; kt <= qbase; kt += 64) {
        __syncthreads();

        load_tile_T(Kb + (size_t)kt * DH, KPs, tid, 1.0f);
        {
            int j = tid >> 4;
            int c = (tid & 15) * 4;
#pragma unroll
            for (int rep = 0; rep < 4; rep++) {
                float4 v = *(const float4*)(Vb + (size_t)(kt + j + rep * 16) * DH + c);
                *(float4*)&Vs[(j + rep * 16) * VS_STRIDE + c] = v;
            }
        }
        if (tid < 64) ms[tid] = mask[b * TT + kt + tid];
        __syncthreads();

        float acc_s[4][4];
#pragma unroll
        for (int i = 0; i < 4; i++)
#pragma unroll
            for (int j = 0; j < 4; j++) acc_s[i][j] = 0.f;

        for (int kk = 0; kk < 64; kk++) {
            float ra[4], rb[4];
#pragma unroll
            for (int i = 0; i < 4; i++) ra[i] = Qs[kk * QS_STRIDE + ty * 4 + i];
#pragma unroll
            for (int j = 0; j < 4; j++) rb[j] = KPs[kk * QS_STRIDE + tx * 4 + j];
#pragma unroll
            for (int i = 0; i < 4; i++)
#pragma unroll
                for (int j = 0; j < 4; j++) acc_s[i][j] += ra[i] * rb[j];
        }
        __syncthreads();

        bool diag = (kt == qbase);

#pragma unroll
        for (int i = 0; i < 4; i++) {
            int il = ty * 4 + i;
            float rmax = -1e30f;
#pragma unroll
            for (int j = 0; j < 4; j++) {
                int jl = tx * 4 + j;
                bool ok = (ms[jl] != 0) && (!diag || jl <= il);
                float s = ok ? acc_s[i][j] : -1e30f;
                acc_s[i][j] = s;
                rmax = fmaxf(rmax, s);
            }
#pragma unroll
            for (int off = 8; off >= 1; off >>= 1)
                rmax = fmaxf(rmax, __shfl_xor_sync(0xffffffffu, rmax, off, 16));
            float m_new = fmaxf(m_r[i], rmax);
            float rsum = 0.f;
#pragma unroll
            for (int j = 0; j < 4; j++) {
                float p = fexp(acc_s[i][j] - m_new);
                acc_s[i][j] = p;
                rsum += p;
            }
#pragma unroll
            for (int off = 8; off >= 1; off >>= 1)
                rsum += __shfl_xor_sync(0xffffffffu, rsum, off, 16);
            float scale = fexp(m_r[i] - m_new);
            l_r[i] = l_r[i] * scale + rsum;
            m_r[i] = m_new;
#pragma unroll
            for (int j = 0; j < 4; j++) acc_o[i][j] *= scale;
        }

#pragma unroll
        for (int i = 0; i < 4; i++)
#pragma unroll
            for (int j = 0; j < 4; j++)
                KPs[(ty * 4 + i) * QS_STRIDE + tx * 4 + j] = acc_s[i][j];
        __syncthreads();

        for (int j = 0; j < 64; j++) {
            float4 vb = *(const float4*)&Vs[j * VS_STRIDE + tx * 4];
            float pa[4];
#pragma unroll
            for (int i = 0; i < 4; i++) pa[i] = KPs[(ty * 4 + i) * QS_STRIDE + j];
#pragma unroll
            for (int i = 0; i < 4; i++) {
                acc_o[i][0] += pa[i] * vb.x;
                acc_o[i][1] += pa[i] * vb.y;
                acc_o[i][2] += pa[i] * vb.z;
                acc_o[i][3] += pa[i] * vb.w;
            }
        }
    }

    // Epilogue: normalize, convert to fp16, write [B*T, D] at head offset
#pragma unroll
    for (int i = 0; i < 4; i++) {
        int il = ty * 4 + i;
        float inv = (l_r[i] > 0.f) ? (1.0f / l_r[i]) : 0.f;
        __half2 h0 = __floats2half2_rn(acc_o[i][0] * inv, acc_o[i][1] * inv);
        __half2 h1 = __floats2half2_rn(acc_o[i][2] * inv, acc_o[i][3] * inv);
        uint2 pk;
        pk.x = *(unsigned*)&h0;
        pk.y = *(unsigned*)&h1;
        *(uint2*)(Out + ((size_t)(b * TT + qbase + il)) * DD + h * DH + tx * 4) = pk;
    }
}

// ---------------------------------------------------------------------------
extern "C" void kernel_launch(void* const* d_in, const int* in_sizes, int n_in,
                              void* d_out, int out_size) {
    const float* x     = (const float*)d_in[0];
    const int*   amask = (const int*)d_in[1];
    const float* Wqkv  = (const float*)d_in[2];
    const float* bqkv  = (const float*)d_in[3];
    const float* Wout  = (const float*)d_in[4];
    const float* bout  = (const float*)d_in[5];
    float* out = (float*)d_out;

    float *qkv, *Qp, *Kp, *Vp;
    __half *xh, *w1h, *w2h, *atth;
    cudaGetSymbolAddress((void**)&qkv,  g_qkv);
    cudaGetSymbolAddress((void**)&Qp,   g_q);
    cudaGetSymbolAddress((void**)&Kp,   g_k);
    cudaGetSymbolAddress((void**)&Vp,   g_v);
    cudaGetSymbolAddress((void**)&xh,   g_xh);
    cudaGetSymbolAddress((void**)&w1h,  g_w1h);
    cudaGetSymbolAddress((void**)&w2h,  g_w2h);
    cudaGetSymbolAddress((void**)&atth, g_atth);

    static bool attr_set = false;
    if (!attr_set) {
        cudaFuncSetAttribute(flash_attn_tiled,
                             cudaFuncAttributeMaxDynamicSharedMemorySize, SMEM_FLASH);
        cudaFuncSetAttribute(gemm_fp16_bias,
                             cudaFuncAttributeMaxDynamicSharedMemorySize, SMEM_GH);
        attr_set = true;
    }

    // 0) Convert GEMM inputs to fp16 once (memory-bound, ~10 us)
    {
        int n4;
        n4 = (BT * DD) / 4;
        to_half_kernel<<<(n4 + 255) / 256, 256>>>(x, xh, n4);
        n4 = (DD * 3 * DD) / 4;
        to_half_kernel<<<(n4 + 255) / 256, 256>>>(Wqkv, w1h, n4);
        n4 = (DD * DD) / 4;
        to_half_kernel<<<(n4 + 255) / 256, 256>>>(Wout, w2h, n4);
    }
    // 1) QKV projection (fp16 wmma, BK=32)
    {
        dim3 grid(3 * DD / BNg, BT / BMg);
        gemm_fp16_bias<<<grid, 256, SMEM_GH>>>(xh, w1h, bqkv, qkv, BT, 3 * DD, DD);
    }
    // 2) RoPE + split
    {
        int total = BB * TT * HH * (DH / 2);
        rope_split_kernel<<<(total + 255) / 256, 256>>>(qkv, Qp, Kp, Vp);
    }
    // 3) Tiled flash attention (R6 kernel; emits fp16 att)
    {
        dim3 grid(TT / 64, HH, BB);
        flash_attn_tiled<<<grid, 256, SMEM_FLASH>>>(Qp, Kp, Vp, amask, atth);
    }
    // 4) Output projection (fp16 wmma)
    {
        dim3 grid(DD / BNg, BT / BMg);
        gemm_fp16_bias<<<grid, 256, SMEM_GH>>>(atth, w2h, bout, out, BT, DD, DD);
    }
}

// round 17
// speedup vs baseline: 1.6176x; 1.1020x over previous
#include <cuda_runtime.h>
#include <stdint.h>
#include <math.h>
#include <mma.h>
#include <cuda_fp16.h>

using namespace nvcuda;

#define BB 2
#define TT 2048
#define DD 1024
#define HH 16
#define DH 64
#define BT (BB*TT)

// Scratch (allocation-free rule: __device__ globals)
__device__ float g_qkv[(size_t)BT * 3 * DD];
__device__ float g_q[(size_t)BT * DD];   // [B,H,T,DH]
__device__ float g_k[(size_t)BT * DD];
__device__ float g_v[(size_t)BT * DD];
__device__ __half g_xh[(size_t)BT * DD];        // x as fp16
__device__ __half g_w1h[(size_t)DD * 3 * DD];   // Wqkv as fp16 [K][N]
__device__ __half g_w2h[(size_t)DD * DD];       // Wout as fp16 [K][N]
__device__ __half g_atth[(size_t)BT * DD];      // att as fp16 (from flash)

// ---------------------------------------------------------------------------
// helpers
// ---------------------------------------------------------------------------
__device__ __forceinline__ void cp_async16(void* dst, const void* src) {
    unsigned int d = (unsigned int)__cvta_generic_to_shared(dst);
    asm volatile("cp.async.ca.shared.global [%0], [%1], 16;\n" :: "r"(d), "l"(src));
}
__device__ __forceinline__ void cp_commit() {
    asm volatile("cp.async.commit_group;\n");
}
__device__ __forceinline__ void cp_wait1() {
    asm volatile("cp.async.wait_group 1;\n");
}
// Fast exp for x <= 0: FFMA/ALU only. rel err ~2e-6.
__device__ __forceinline__ float fexp(float x) {
    float t = fmaxf(x * 1.4426950408889634f, -126.0f);
    float tr = t + 12582912.0f;
    int   n  = __float_as_int(tr) - 0x4B400000;
    float f  = t - (tr - 12582912.0f);
    float p = 0.0013333558f;
    p = fmaf(p, f, 0.0096181291f);
    p = fmaf(p, f, 0.0555041087f);
    p = fmaf(p, f, 0.2402265069f);
    p = fmaf(p, f, 0.6931471806f);
    p = fmaf(p, f, 1.0f);
    return p * __int_as_float((n + 127) << 23);
}

// Packed f32x2 ops (Blackwell FFMA2 path; bit-exact = two fp32 ops)
__device__ __forceinline__ unsigned long long pk2(float lo, float hi) {
    unsigned long long r;
    asm("mov.b64 %0, {%1, %2};" : "=l"(r) : "f"(lo), "f"(hi));
    return r;
}
__device__ __forceinline__ void upk2(unsigned long long p, float& lo, float& hi) {
    asm("mov.b64 {%0, %1}, %2;" : "=f"(lo), "=f"(hi) : "l"(p));
}
__device__ __forceinline__ unsigned long long fma2(unsigned long long a,
                                                   unsigned long long b,
                                                   unsigned long long c) {
    unsigned long long d;
    asm("fma.rn.f32x2 %0, %1, %2, %3;" : "=l"(d) : "l"(a), "l"(b), "l"(c));
    return d;
}
__device__ __forceinline__ unsigned long long mul2(unsigned long long a,
                                                   unsigned long long b) {
    unsigned long long d;
    asm("mul.rn.f32x2 %0, %1, %2;" : "=l"(d) : "l"(a), "l"(b));
    return d;
}

// Elementwise f32 -> fp16 conversion (memory-bound, run once per buffer)
__global__ __launch_bounds__(256)
void to_half_kernel(const float* __restrict__ in, __half* __restrict__ out, int n4) {
    int i = blockIdx.x * blockDim.x + threadIdx.x;
    if (i >= n4) return;
    float4 v = ((const float4*)in)[i];
    __half2 h0 = __floats2half2_rn(v.x, v.y);
    __half2 h1 = __floats2half2_rn(v.z, v.w);
    uint2 pk;
    pk.x = *(unsigned*)&h0;
    pk.y = *(unsigned*)&h1;
    ((uint2*)out)[i] = pk;
}

// ---------------------------------------------------------------------------
// FP16 tensor-core GEMM (R13, measured QKV=105us). Unchanged.
// ---------------------------------------------------------------------------
#define BMg 128
#define BNg 128
#define BKh 32
#define STAGES 3
#define A_ST 40
#define B_ST 136
#define AS_T (BMg * A_ST)
#define BS_T (BKh * B_ST)
#define SMEM_GH ((STAGES * (AS_T + BS_T)) * 2)

__global__ __launch_bounds__(256, 2)
void gemm_fp16_bias(const __half* __restrict__ A, const __half* __restrict__ B,
                    const float* __restrict__ bias, float* __restrict__ C,
                    int M, int N, int K) {
    extern __shared__ __half smh[];
    __half* AsBase = smh;
    __half* BsBase = smh + STAGES * AS_T;

    int tid  = threadIdx.x;
    int wid  = tid >> 5;
    int lane = tid & 31;
    int warp_m = wid & 3;
    int warp_n = wid >> 2;
    int brow = blockIdx.y * BMg;
    int bcol = blockIdx.x * BNg;

    int a_row = tid >> 1;
    int a_col = (tid & 1) * 16;
    int b_row = tid >> 3;
    int b_col = (tid & 7) * 16;

    const __half* Ap = A + (size_t)(brow + a_row) * K + a_col;
    const __half* Bp = B + (size_t)b_row * N + bcol + b_col;

    wmma::fragment<wmma::accumulator, 16, 16, 16, float> acc[2][4];
#pragma unroll
    for (int i = 0; i < 2; i++)
#pragma unroll
        for (int j = 0; j < 4; j++) wmma::fill_fragment(acc[i][j], 0.0f);

    const int iters = K / BKh;

#pragma unroll
    for (int s = 0; s < STAGES - 1; s++) {
        int k0 = s * BKh;
        __half* As = AsBase + s * AS_T;
        __half* Bs = BsBase + s * BS_T;
        cp_async16(&As[a_row * A_ST + a_col],     Ap + k0);
        cp_async16(&As[a_row * A_ST + a_col + 8], Ap + k0 + 8);
        cp_async16(&Bs[b_row * B_ST + b_col],     Bp + (size_t)k0 * N);
        cp_async16(&Bs[b_row * B_ST + b_col + 8], Bp + (size_t)k0 * N + 8);
        cp_commit();
    }

    for (int it = 0; it < iters; it++) {
        cp_wait1();
        __syncthreads();

        int buf = it % STAGES;
        __half* As = AsBase + buf * AS_T;
        __half* Bs = BsBase + buf * BS_T;

#pragma unroll
        for (int kk = 0; kk < BKh; kk += 16) {
            wmma::fragment<wmma::matrix_a, 16, 16, 16, __half, wmma::row_major> af[2];
            wmma::fragment<wmma::matrix_b, 16, 16, 16, __half, wmma::row_major> bf[4];
#pragma unroll
            for (int i = 0; i < 2; i++)
                wmma::load_matrix_sync(af[i], &As[(warp_m * 32 + i * 16) * A_ST + kk], A_ST);
#pragma unroll
            for (int j = 0; j < 4; j++)
                wmma::load_matrix_sync(bf[j], &Bs[kk * B_ST + warp_n * 64 + j * 16], B_ST);
#pragma unroll
            for (int i = 0; i < 2; i++)
#pragma unroll
                for (int j = 0; j < 4; j++)
                    wmma::mma_sync(acc[i][j], af[i], bf[j], acc[i][j]);
        }

        int k_next = (it + STAGES - 1) * BKh;
        if (k_next < K) {
            int s = (it + STAGES - 1) % STAGES;
            __half* Asn = AsBase + s * AS_T;
            __half* Bsn = BsBase + s * BS_T;
            cp_async16(&Asn[a_row * A_ST + a_col],     Ap + k_next);
            cp_async16(&Asn[a_row * A_ST + a_col + 8], Ap + k_next + 8);
            cp_async16(&Bsn[b_row * B_ST + b_col],     Bp + (size_t)k_next * N);
            cp_async16(&Bsn[b_row * B_ST + b_col + 8], Bp + (size_t)k_next * N + 8);
        }
        cp_commit();
    }

    __syncthreads();
    float* stg = (float*)smh + wid * 16 * 24;

    int er = lane >> 1;
    int ec = (lane & 1) * 8;
#pragma unroll
    for (int i = 0; i < 2; i++) {
#pragma unroll
        for (int j = 0; j < 4; j++) {
            wmma::store_matrix_sync(stg, acc[i][j], 24, wmma::mem_row_major);
            __syncwarp();
            int gr = brow + warp_m * 32 + i * 16 + er;
            int gc = bcol + warp_n * 64 + j * 16 + ec;
            float4 v0 = *(float4*)&stg[er * 24 + ec];
            float4 v1 = *(float4*)&stg[er * 24 + ec + 4];
            const float4 bb0 = *(const float4*)&bias[gc];
            const float4 bb1 = *(const float4*)&bias[gc + 4];
            v0.x += bb0.x; v0.y += bb0.y; v0.z += bb0.z; v0.w += bb0.w;
            v1.x += bb1.x; v1.y += bb1.y; v1.z += bb1.z; v1.w += bb1.w;
            *(float4*)(C + (size_t)gr * N + gc)     = v0;
            *(float4*)(C + (size_t)gr * N + gc + 4) = v1;
            __syncwarp();
        }
    }
}

// ---------------------------------------------------------------------------
// RoPE + split qkv[BT, 3D] -> Q,K,V in [B,H,T,DH]  (float, R13-verbatim)
// ---------------------------------------------------------------------------
__global__ __launch_bounds__(256)
void rope_split_kernel(const float* __restrict__ qkv,
                       float* __restrict__ Q, float* __restrict__ K,
                       float* __restrict__ V) {
    int idx = blockIdx.x * blockDim.x + threadIdx.x;
    const int total = BB * TT * HH * (DH / 2);
    if (idx >= total) return;
    int d2 = idx & 31;
    int h  = (idx >> 5) & (HH - 1);
    int t  = (idx >> 9) & (TT - 1);
    int b  = idx >> 20;

    size_t row = (size_t)b * TT + t;
    const float* qr = qkv + row * (3 * DD) + h * DH + 2 * d2;
    const float* kr = qr + DD;
    const float* vr = qr + 2 * DD;

    float inv_freq = powf(10000.0f, -((float)(2 * d2)) / (float)DH);
    float freq = (float)t * inv_freq;
    float s = sinf(freq);
    float c = cosf(freq);

    float qe = qr[0], qo = qr[1];
    float ke = kr[0], ko = kr[1];

    size_t o = ((((size_t)b * HH + h) * TT) + t) * DH + 2 * d2;
    Q[o]     = qe * c - qo * s;
    Q[o + 1] = qe * s + qo * c;
    K[o]     = ke * c - ko * s;
    K[o + 1] = ke * s + ko * c;
    V[o]     = vr[0];
    V[o + 1] = vr[1];
}

// ---------------------------------------------------------------------------
// Tiled flash attention: R6/R13 structure with f32x2 packed-FMA inner loops.
// Strides 65 -> 68 (float4-aligned rows); math bit-identical to scalar fp32.
// Epilogue writes att as fp16 (feeds the fp16 out-projection).
// ---------------------------------------------------------------------------
#define FS 68
#define SMEM_FLASH ((3 * 64 * FS) * 4 + 64 * 4)

__device__ __forceinline__ void load_tile_T68(const float* __restrict__ src,
                                              float* __restrict__ dst,
                                              int tid, float mul) {
    int r = tid >> 2;
    int cbase = (tid & 3) * 4;
#pragma unroll
    for (int rep = 0; rep < 4; rep++) {
        int c = cbase + rep * 16;
        float4 v = *(const float4*)(src + r * 64 + c);
        dst[(c + 0) * FS + r] = v.x * mul;
        dst[(c + 1) * FS + r] = v.y * mul;
        dst[(c + 2) * FS + r] = v.z * mul;
        dst[(c + 3) * FS + r] = v.w * mul;
    }
}

__global__ __launch_bounds__(256)
void flash_attn_tiled(const float* __restrict__ Q, const float* __restrict__ K,
                      const float* __restrict__ V, const int* __restrict__ mask,
                      __half* __restrict__ Out) {
    extern __shared__ float sm[];
    float* Qs  = sm;                 // [d][query] transposed, prescaled
    float* KPs = sm + 64 * FS;       // K^T [d][key] then P [row][key]
    float* Vs  = sm + 2 * 64 * FS;   // [key][d]
    int*   ms  = (int*)(sm + 3 * 64 * FS);

    int b = blockIdx.z, h = blockIdx.y;
    int qtile = gridDim.x - 1 - blockIdx.x;
    int qbase = qtile * 64;
    int tid = threadIdx.x;
    int ty = tid >> 4;
    int tx = tid & 15;

    const size_t bh = ((size_t)b * HH + h) * TT;
    const float* Qb = Q + bh * DH;
    const float* Kb = K + bh * DH;
    const float* Vb = V + bh * DH;

    load_tile_T68(Qb + (size_t)qbase * DH, Qs, tid, 0.125f);

    unsigned long long o2[4][2];     // packed O accumulator: [row][pair]
    float m_r[4], l_r[4];
#pragma unroll
    for (int i = 0; i < 4; i++) {
        m_r[i] = -1e30f;
        l_r[i] = 0.f;
        o2[i][0] = 0ull;
        o2[i][1] = 0ull;
    }

    for (int kt = 0; kt <= qbase; kt += 64) {
        __syncthreads();

        load_tile_T68(Kb + (size_t)kt * DH, KPs, tid, 1.0f);
        {
            int j = tid >> 4;
            int c = (tid & 15) * 4;
#pragma unroll
            for (int rep = 0; rep < 4; rep++) {
                float4 v = *(const float4*)(Vb + (size_t)(kt + j + rep * 16) * DH + c);
                *(float4*)&Vs[(j + rep * 16) * FS + c] = v;
            }
        }
        if (tid < 64) ms[tid] = mask[b * TT + kt + tid];
        __syncthreads();

        // ---- S = Q*K^T : packed f32x2 FMA, 2x LDS.128 per kk ----
        unsigned long long s2[4][2];
#pragma unroll
        for (int i = 0; i < 4; i++) { s2[i][0] = 0ull; s2[i][1] = 0ull; }

        for (int kk = 0; kk < 64; kk++) {
            float4 ra = *(const float4*)&Qs[kk * FS + ty * 4];
            float4 rb = *(const float4*)&KPs[kk * FS + tx * 4];
            unsigned long long rb0 = pk2(rb.x, rb.y);
            unsigned long long rb1 = pk2(rb.z, rb.w);
            unsigned long long ap;
            ap = pk2(ra.x, ra.x);
            s2[0][0] = fma2(ap, rb0, s2[0][0]); s2[0][1] = fma2(ap, rb1, s2[0][1]);
            ap = pk2(ra.y, ra.y);
            s2[1][0] = fma2(ap, rb0, s2[1][0]); s2[1][1] = fma2(ap, rb1, s2[1][1]);
            ap = pk2(ra.z, ra.z);
            s2[2][0] = fma2(ap, rb0, s2[2][0]); s2[2][1] = fma2(ap, rb1, s2[2][1]);
            ap = pk2(ra.w, ra.w);
            s2[3][0] = fma2(ap, rb0, s2[3][0]); s2[3][1] = fma2(ap, rb1, s2[3][1]);
        }
        __syncthreads();   // done reading K^T; KPs becomes P

        bool diag = (kt == qbase);

        // ---- Online softmax (unpack, scalar math, P into KPs) ----
#pragma unroll
        for (int i = 0; i < 4; i++) {
            int il = ty * 4 + i;
            float sv[4];
            upk2(s2[i][0], sv[0], sv[1]);
            upk2(s2[i][1], sv[2], sv[3]);
            float rmax = -1e30f;
#pragma unroll
            for (int j = 0; j < 4; j++) {
                int jl = tx * 4 + j;
                bool ok = (ms[jl] != 0) && (!diag || jl <= il);
                float s = ok ? sv[j] : -1e30f;
                sv[j] = s;
                rmax = fmaxf(rmax, s);
            }
#pragma unroll
            for (int off = 8; off >= 1; off >>= 1)
                rmax = fmaxf(rmax, __shfl_xor_sync(0xffffffffu, rmax, off, 16));
            float m_new = fmaxf(m_r[i], rmax);
            float rsum = 0.f;
#pragma unroll
            for (int j = 0; j < 4; j++) {
                float p = fexp(sv[j] - m_new);
                KPs[il * FS + tx * 4 + j] = p;
                rsum += p;
            }
#pragma unroll
            for (int off = 8; off >= 1; off >>= 1)
                rsum += __shfl_xor_sync(0xffffffffu, rsum, off, 16);
            float scale = fexp(m_r[i] - m_new);
            l_r[i] = l_r[i] * scale + rsum;
            m_r[i] = m_new;
            unsigned long long sc2 = pk2(scale, scale);
            o2[i][0] = mul2(o2[i][0], sc2);
            o2[i][1] = mul2(o2[i][1], sc2);
        }
        __syncthreads();

        // ---- O += P*V : packed f32x2 FMA ----
        for (int j = 0; j < 64; j++) {
            float4 vb = *(const float4*)&Vs[j * FS + tx * 4];
            unsigned long long vb0 = pk2(vb.x, vb.y);
            unsigned long long vb1 = pk2(vb.z, vb.w);
#pragma unroll
            for (int i = 0; i < 4; i++) {
                float pa = KPs[(ty * 4 + i) * FS + j];
                unsigned long long pp = pk2(pa, pa);
                o2[i][0] = fma2(pp, vb0, o2[i][0]);
                o2[i][1] = fma2(pp, vb1, o2[i][1]);
            }
        }
    }

    // Epilogue: unpack, normalize, convert to fp16, write
#pragma unroll
    for (int i = 0; i < 4; i++) {
        int il = ty * 4 + i;
        float inv = (l_r[i] > 0.f) ? (1.0f / l_r[i]) : 0.f;
        float o0, o1, o2f, o3;
        upk2(o2[i][0], o0, o1);
        upk2(o2[i][1], o2f, o3);
        __half2 h0 = __floats2half2_rn(o0 * inv, o1 * inv);
        __half2 h1 = __floats2half2_rn(o2f * inv, o3 * inv);
        uint2 pk;
        pk.x = *(unsigned*)&h0;
        pk.y = *(unsigned*)&h1;
        *(uint2*)(Out + ((size_t)(b * TT + qbase + il)) * DD + h * DH + tx * 4) = pk;
    }
}

// ---------------------------------------------------------------------------
extern "C" void kernel_launch(void* const* d_in, const int* in_sizes, int n_in,
                              void* d_out, int out_size) {
    const float* x     = (const float*)d_in[0];
    const int*   amask = (const int*)d_in[1];
    const float* Wqkv  = (const float*)d_in[2];
    const float* bqkv  = (const float*)d_in[3];
    const float* Wout  = (const float*)d_in[4];
    const float* bout  = (const float*)d_in[5];
    float* out = (float*)d_out;

    float *qkv, *Qp, *Kp, *Vp;
    __half *xh, *w1h, *w2h, *atth;
    cudaGetSymbolAddress((void**)&qkv,  g_qkv);
    cudaGetSymbolAddress((void**)&Qp,   g_q);
    cudaGetSymbolAddress((void**)&Kp,   g_k);
    cudaGetSymbolAddress((void**)&Vp,   g_v);
    cudaGetSymbolAddress((void**)&xh,   g_xh);
    cudaGetSymbolAddress((void**)&w1h,  g_w1h);
    cudaGetSymbolAddress((void**)&w2h,  g_w2h);
    cudaGetSymbolAddress((void**)&atth, g_atth);

    static bool attr_set = false;
    if (!attr_set) {
        cudaFuncSetAttribute(flash_attn_tiled,
                             cudaFuncAttributeMaxDynamicSharedMemorySize, SMEM_FLASH);
        cudaFuncSetAttribute(gemm_fp16_bias,
                             cudaFuncAttributeMaxDynamicSharedMemorySize, SMEM_GH);
        attr_set = true;
    }

    // 0) Convert GEMM inputs to fp16 once (memory-bound)
    {
        int n4;
        n4 = (BT * DD) / 4;
        to_half_kernel<<<(n4 + 255) / 256, 256>>>(x, xh, n4);
        n4 = (DD * 3 * DD) / 4;
        to_half_kernel<<<(n4 + 255) / 256, 256>>>(Wqkv, w1h, n4);
        n4 = (DD * DD) / 4;
        to_half_kernel<<<(n4 + 255) / 256, 256>>>(Wout, w2h, n4);
    }
    // 1) QKV projection (fp16 wmma)
    {
        dim3 grid(3 * DD / BNg, BT / BMg);
        gemm_fp16_bias<<<grid, 256, SMEM_GH>>>(xh, w1h, bqkv, qkv, BT, 3 * DD, DD);
    }
    // 2) RoPE + split (float)
    {
        int total = BB * TT * HH * (DH / 2);
        rope_split_kernel<<<(total + 255) / 256, 256>>>(qkv, Qp, Kp, Vp);
    }
    // 3) Tiled flash attention (f32x2 packed FMA; emits fp16 att)
    {
        dim3 grid(TT / 64, HH, BB);
        flash_attn_tiled<<<grid, 256, SMEM_FLASH>>>(Qp, Kp, Vp, amask, atth);
    }
    // 4) Output projection (fp16 wmma)
    {
        dim3 grid(DD / BNg, BT / BMg);
        gemm_fp16_bias<<<grid, 256, SMEM_GH>>>(atth, w2h, bout, out, BT, DD, DD);
    }
}